// round 3
// baseline (speedup 1.0000x reference)
#include <cuda_runtime.h>

// PixelRNN: 2-layer LSTM over T=4096 raster steps, B=256, H=128, OUT=45.
// Persistent cooperative kernel, 1 global barrier per timestep, software-
// pipelined (layer0@s, layer1@s-1, out-proj@s-2), c-state in registers,
// weights in SMEM, h0/h1 double-buffered in L2 (.cg loads/stores).
// Co-residency: 128 CTAs, 112KB dyn smem forces 1 CTA/SM on 148 SMs ->
// all CTAs are wave-1 resident, so the global spin barrier cannot deadlock.

#define TSEQ   4096
#define BATCH  256
#define HSZ    128
#define NOUT   45
#define NCTA   128     // 4 batch tiles x 32 u-groups
#define NTH    256
#define BTILE  64      // batch rows per CTA
#define UPG    4       // hidden units per CTA

// ---- persistent device state (allowed scratch) ----
__device__ float g_h0T[2 * HSZ * BATCH];   // [parity][k][b]
__device__ float g_h1T[2 * HSZ * BATCH];
__device__ float g_Mf[512 * 4];            // folded input path: [j][c0,c1,c2,bias0]
__device__ float g_bias1[512];
__device__ unsigned int g_bar;

__global__ void zero_init_kernel() {
    int idx = blockIdx.x * blockDim.x + threadIdx.x;
    int stride = gridDim.x * blockDim.x;
    for (int i = idx; i < 2 * HSZ * BATCH; i += stride) {
        g_h0T[i] = 0.f;
        g_h1T[i] = 0.f;
    }
    if (idx == 0) g_bar = 0u;
}

// Fold: gates0 pre-activation = px @ (W_ih0 @ W_in)^T + (b_ih0 + b_hh0 + W_ih0 @ b_in)
__global__ void fold_kernel(const float* __restrict__ W_in, const float* __restrict__ b_in,
                            const float* __restrict__ W_ih, const float* __restrict__ b_ih,
                            const float* __restrict__ b_hh) {
    int j = blockIdx.x * blockDim.x + threadIdx.x;  // 0..511
    if (j < 512) {
        float m0 = 0.f, m1 = 0.f, m2 = 0.f, mb = 0.f;
        for (int k = 0; k < HSZ; ++k) {
            float w = W_ih[j * HSZ + k];             // layer 0
            m0 += w * W_in[k * 3 + 0];
            m1 += w * W_in[k * 3 + 1];
            m2 += w * W_in[k * 3 + 2];
            mb += w * b_in[k];
        }
        g_Mf[j * 4 + 0] = m0;
        g_Mf[j * 4 + 1] = m1;
        g_Mf[j * 4 + 2] = m2;
        g_Mf[j * 4 + 3] = mb + b_ih[j] + b_hh[j];
        g_bias1[j] = b_ih[512 + j] + b_hh[512 + j];
    }
}

__device__ __forceinline__ float sigf(float v)  { return 1.0f / (1.0f + __expf(-v)); }
__device__ __forceinline__ float tanh_(float v) { return 1.0f - 2.0f / (__expf(2.0f * v) + 1.0f); }

// SMEM layout (floats)
#define SM_H0S  0                    // [128][64]
#define SM_H1S  8192                 // [128][64]
#define SM_W0S  16384                // [128][16]  layer0 Whh slice, [k][ul*4+g]
#define SM_W1S  18432                // [128][32]  layer1 Wih/Whh slice, [k][ul*8 + mat*4 + g]
#define SM_WOT  22528                // [128][48]  W_out^T padded
#define SM_BO   28672                // [48]
#define SM_FLOATS 28720
#define SMEM_BYTES (SM_FLOATS * 4)

__global__ void __launch_bounds__(NTH, 1) lstm_persist(
    const float* __restrict__ x,      // [B,3,64,64]
    const float* __restrict__ W_ih,   // [2,512,128]
    const float* __restrict__ W_hh,   // [2,512,128]
    const float* __restrict__ W_out,  // [45,128]
    const float* __restrict__ b_out,  // [45]
    float* __restrict__ out)          // [B,T,45]
{
    extern __shared__ float sm[];
    float* h0s = sm + SM_H0S;
    float* h1s = sm + SM_H1S;
    float* W0s = sm + SM_W0S;
    float* W1s = sm + SM_W1S;
    float* WoT = sm + SM_WOT;
    float* bo  = sm + SM_BO;

    const int tid = threadIdx.x;
    const int bt = blockIdx.x & 3;
    const int ug = blockIdx.x >> 2;        // 0..31
    const int b0 = bt * BTILE;
    const int uStart = ug * UPG;

    // ---- one-time weight staging ----
    for (int i = tid; i < 16 * HSZ; i += NTH) {
        int colg = i >> 7, k = i & 127;            // colg = ul*4+g
        int ul = colg >> 2, g = colg & 3;
        W0s[k * 16 + colg] = __ldg(&W_hh[(uStart + ul + g * HSZ) * HSZ + k]);  // layer0 hh
    }
    for (int i = tid; i < 32 * HSZ; i += NTH) {
        int col = i >> 7, k = i & 127;             // col = ul*8 + mat*4 + g
        int ul = col >> 3, mt = (col >> 2) & 1, g = col & 3;
        const float* src = mt ? (W_hh + 512 * HSZ) : (W_ih + 512 * HSZ);
        W1s[k * 32 + col] = __ldg(&src[(uStart + ul + g * HSZ) * HSZ + k]);
    }
    for (int i = tid; i < NOUT * HSZ; i += NTH) {
        int o = i >> 7, k = i & 127;
        WoT[k * 48 + o] = __ldg(&W_out[o * HSZ + k]);
    }
    if (tid < NOUT) bo[tid] = __ldg(&b_out[tid]);
    __syncthreads();

    const int bl = tid & 63;
    const int b  = b0 + bl;
    const int ul = tid >> 6;
    const int u  = uStart + ul;

    float c0r = 0.f, c1r = 0.f;   // cell states live in registers for all 4096 steps

    const float4 mi = *reinterpret_cast<const float4*>(&g_Mf[(u        ) * 4]);
    const float4 mf = *reinterpret_cast<const float4*>(&g_Mf[(u + 128) * 4]);
    const float4 mg = *reinterpret_cast<const float4*>(&g_Mf[(u + 256) * 4]);
    const float4 mo = *reinterpret_cast<const float4*>(&g_Mf[(u + 384) * 4]);
    const float bi1 = g_bias1[u], bf1 = g_bias1[u + 128];
    const float bg1 = g_bias1[u + 256], bo1 = g_bias1[u + 384];

    const float* xrow = x + b * 3 * TSEQ;

    for (int s = 0; s <= TSEQ + 1; ++s) {
        const int rp  = (s + 1) & 1;   // == (s-1)&1 : h0 prev parity
        const int rp2 = s & 1;         // == (s-2)&1 : h1 prev parity

        // ---- stage h0_{s-1} and h1_{s-2} slices into SMEM (L2-coherent loads)
        for (int i = tid; i < HSZ * 16; i += NTH) {
            int k = i >> 4, c = i & 15;
            float4 v0 = __ldcg(reinterpret_cast<const float4*>(&g_h0T[(rp  * HSZ + k) * BATCH + b0]) + c);
            reinterpret_cast<float4*>(h0s)[i] = v0;
            float4 v1 = __ldcg(reinterpret_cast<const float4*>(&g_h1T[(rp2 * HSZ + k) * BATCH + b0]) + c);
            reinterpret_cast<float4*>(h1s)[i] = v1;
        }
        __syncthreads();

        // ---- layer 0, step s: gates = folded(px) + h0_{s-1} @ Whh0^T
        if (s < TSEQ) {
            const float px0 = __ldg(xrow + s);
            const float px1 = __ldg(xrow + TSEQ + s);
            const float px2 = __ldg(xrow + 2 * TSEQ + s);
            float ai = mi.x * px0 + mi.y * px1 + mi.z * px2 + mi.w;
            float af = mf.x * px0 + mf.y * px1 + mf.z * px2 + mf.w;
            float ag = mg.x * px0 + mg.y * px1 + mg.z * px2 + mg.w;
            float ao = mo.x * px0 + mo.y * px1 + mo.z * px2 + mo.w;
            const float* wp = W0s + ul * 4;
            const float* hp = h0s + bl;
            #pragma unroll 8
            for (int k = 0; k < HSZ; ++k) {
                float hk = hp[k * 64];
                float4 w = *reinterpret_cast<const float4*>(wp + k * 16);
                ai += hk * w.x; af += hk * w.y; ag += hk * w.z; ao += hk * w.w;
            }
            float I = sigf(ai), F = sigf(af), G = tanh_(ag), O = sigf(ao);
            c0r = F * c0r + I * G;
            float h = O * tanh_(c0r);
            __stcg(&g_h0T[((s & 1) * HSZ + u) * BATCH + b], h);
        }

        // ---- layer 1, step s-1: gates = h0_{s-1} @ Wih1^T + h1_{s-2} @ Whh1^T
        if (s >= 1 && s <= TSEQ) {
            float ai0 = bi1, af0 = bf1, ag0 = bg1, ao0 = bo1;
            float ai1 = 0.f, af1 = 0.f, ag1 = 0.f, ao1 = 0.f;
            const float* wp1 = W1s + ul * 8;
            const float* hp0 = h0s + bl;
            const float* hp1 = h1s + bl;
            #pragma unroll 4
            for (int k = 0; k < HSZ; ++k) {
                float h0k = hp0[k * 64];
                float h1k = hp1[k * 64];
                float4 wi4 = *reinterpret_cast<const float4*>(wp1 + k * 32);
                float4 wh4 = *reinterpret_cast<const float4*>(wp1 + k * 32 + 4);
                ai0 += h0k * wi4.x; af0 += h0k * wi4.y; ag0 += h0k * wi4.z; ao0 += h0k * wi4.w;
                ai1 += h1k * wh4.x; af1 += h1k * wh4.y; ag1 += h1k * wh4.z; ao1 += h1k * wh4.w;
            }
            float I = sigf(ai0 + ai1), F = sigf(af0 + af1);
            float G = tanh_(ag0 + ag1), O = sigf(ao0 + ao1);
            c1r = F * c1r + I * G;
            float h = O * tanh_(c1r);
            __stcg(&g_h1T[(((s - 1) & 1) * HSZ + u) * BATCH + b], h);
        }

        // ---- output projection, step s-2 (h1s staged buffer == h1_{s-2})
        if (s >= 2 && tid < 90) {
            int d = ug * 90 + tid;             // 32 u-groups * 90 = 64 b * 45 outs
            int blo = d / 45, o = d % 45;
            float acc = bo[o];
            const float* hp  = h1s + blo;
            const float* wpo = WoT + o;
            #pragma unroll 8
            for (int k = 0; k < HSZ; ++k) acc += hp[k * 64] * wpo[k * 48];
            out[(b0 + blo) * (TSEQ * NOUT) + (s - 2) * NOUT + o] = acc;
        }

        // ---- global barrier (one per step): arrive, then backoff-spin
        __syncthreads();
        if (tid == 0) {
            __threadfence();
            atomicAdd(&g_bar, 1u);
            const unsigned target = (unsigned)(s + 1) * (unsigned)NCTA;
            while (*reinterpret_cast<volatile unsigned*>(&g_bar) < target) {
                __nanosleep(64);
            }
            __threadfence();
        }
        __syncthreads();
    }
}

extern "C" void kernel_launch(void* const* d_in, const int* in_sizes, int n_in,
                              void* d_out, int out_size) {
    const float* x     = (const float*)d_in[0];
    const float* W_in  = (const float*)d_in[1];
    const float* b_in  = (const float*)d_in[2];
    const float* W_ih  = (const float*)d_in[3];
    const float* W_hh  = (const float*)d_in[4];
    const float* b_ih  = (const float*)d_in[5];
    const float* b_hh  = (const float*)d_in[6];
    const float* W_out = (const float*)d_in[7];
    const float* b_out = (const float*)d_in[8];
    float* out = (float*)d_out;

    cudaFuncSetAttribute(lstm_persist, cudaFuncAttributeMaxDynamicSharedMemorySize, SMEM_BYTES);

    zero_init_kernel<<<64, 256>>>();
    fold_kernel<<<4, 128>>>(W_in, b_in, W_ih, b_ih, b_hh);
    lstm_persist<<<NCTA, NTH, SMEM_BYTES>>>(x, W_ih, W_hh, W_out, b_out, out);
}

// round 5
// speedup vs baseline: 1.0324x; 1.0324x over previous
#include <cuda_runtime.h>

// PixelRNN: 2-layer LSTM, T=4096 steps, B=256, H=128, OUT=45.
// Persistent cooperative kernel, flag-based release/acquire global barrier
// (1 per step), software-pipelined (layer0@s, layer1@s-1, out-proj@s-2),
// c-state in registers, weights in SMEM, h0/h1 double-buffered via L2 (.cg),
// packed fma.rn.f32x2 for the gate accumulations.
// Co-residency: 128 CTAs, 112KB dyn smem -> 1 CTA/SM, all wave-1 resident.

#define TSEQ   4096
#define BATCH  256
#define HSZ    128
#define NOUT   45
#define NCTA   128     // 4 batch tiles x 32 u-groups
#define NTH    256
#define BTILE  64      // batch rows per CTA
#define UPG    4       // hidden units per CTA

// ---- persistent device state ----
__device__ float g_h0T[2 * HSZ * BATCH];   // [parity][k][b]
__device__ float g_h1T[2 * HSZ * BATCH];
__device__ float g_Mf[512 * 4];            // folded input path: [j][c0,c1,c2,bias0]
__device__ float g_bias1[512];
__device__ unsigned int g_flags[NCTA * 32];  // 128B-padded per-CTA barrier flags

// Merged init: zero h/flags + fold input path (2 launches/call total, so
// ncu -s 5 -c 1 lands on lstm_persist during graph replay).
__global__ void prep_kernel(const float* __restrict__ W_in, const float* __restrict__ b_in,
                            const float* __restrict__ W_ih, const float* __restrict__ b_ih,
                            const float* __restrict__ b_hh) {
    int idx = blockIdx.x * blockDim.x + threadIdx.x;
    int stride = gridDim.x * blockDim.x;
    for (int i = idx; i < 2 * HSZ * BATCH; i += stride) {
        g_h0T[i] = 0.f;
        g_h1T[i] = 0.f;
    }
    for (int i = idx; i < NCTA * 32; i += stride) g_flags[i] = 0u;
    int j = idx;
    if (j < 512) {
        float m0 = 0.f, m1 = 0.f, m2 = 0.f, mb = 0.f;
        for (int k = 0; k < HSZ; ++k) {
            float w = W_ih[j * HSZ + k];             // layer 0
            m0 += w * W_in[k * 3 + 0];
            m1 += w * W_in[k * 3 + 1];
            m2 += w * W_in[k * 3 + 2];
            mb += w * b_in[k];
        }
        g_Mf[j * 4 + 0] = m0;
        g_Mf[j * 4 + 1] = m1;
        g_Mf[j * 4 + 2] = m2;
        g_Mf[j * 4 + 3] = mb + b_ih[j] + b_hh[j];
        g_bias1[j] = b_ih[512 + j] + b_hh[512 + j];
    }
}

__device__ __forceinline__ float sigf(float v)  { return 1.0f / (1.0f + __expf(-v)); }
__device__ __forceinline__ float tanh_(float v) { return 1.0f - 2.0f / (__expf(2.0f * v) + 1.0f); }

__device__ __forceinline__ unsigned long long pack2(float lo, float hi) {
    unsigned long long r;
    asm("mov.b64 %0, {%1, %2};" : "=l"(r) : "f"(lo), "f"(hi));
    return r;
}
__device__ __forceinline__ unsigned long long packdup(float v) {
    unsigned long long r;
    asm("mov.b64 %0, {%1, %1};" : "=l"(r) : "f"(v));
    return r;
}
__device__ __forceinline__ void fma2(unsigned long long& acc, unsigned long long a, unsigned long long b) {
    asm("fma.rn.f32x2 %0, %1, %2, %0;" : "+l"(acc) : "l"(a), "l"(b));
}
__device__ __forceinline__ void unpack2(float& lo, float& hi, unsigned long long v) {
    asm("mov.b64 {%0, %1}, %2;" : "=f"(lo), "=f"(hi) : "l"(v));
}

// SMEM layout (floats)
#define SM_H0S  0                    // [128][64]
#define SM_H1S  8192                 // [128][64]
#define SM_W0S  16384                // [128][16]  layer0 Whh slice, [k][ul*4+g] g=i,f,g,o
#define SM_W1S  18432                // [128][32]  layer1, [k][ul*8 + mat*4 + g]
#define SM_WOT  22528                // [128][48]  W_out^T padded
#define SM_BO   28672                // [48]
#define SM_FLOATS 28720
#define SMEM_BYTES (SM_FLOATS * 4)

__global__ void __launch_bounds__(NTH, 1) lstm_persist(
    const float* __restrict__ x,      // [B,3,64,64]
    const float* __restrict__ W_ih,   // [2,512,128]
    const float* __restrict__ W_hh,   // [2,512,128]
    const float* __restrict__ W_out,  // [45,128]
    const float* __restrict__ b_out,  // [45]
    float* __restrict__ out)          // [B,T,45]
{
    extern __shared__ float sm[];
    float* h0s = sm + SM_H0S;
    float* h1s = sm + SM_H1S;
    float* W0s = sm + SM_W0S;
    float* W1s = sm + SM_W1S;
    float* WoT = sm + SM_WOT;
    float* bo  = sm + SM_BO;

    const int tid = threadIdx.x;
    const int bt = blockIdx.x & 3;
    const int ug = blockIdx.x >> 2;        // 0..31
    const int b0 = bt * BTILE;
    const int uStart = ug * UPG;

    // ---- one-time weight staging ----
    for (int i = tid; i < 16 * HSZ; i += NTH) {
        int colg = i >> 7, k = i & 127;            // colg = ul*4+g
        int ul = colg >> 2, g = colg & 3;
        W0s[k * 16 + colg] = __ldg(&W_hh[(uStart + ul + g * HSZ) * HSZ + k]);  // layer0 hh
    }
    for (int i = tid; i < 32 * HSZ; i += NTH) {
        int col = i >> 7, k = i & 127;             // col = ul*8 + mat*4 + g
        int ul = col >> 3, mt = (col >> 2) & 1, g = col & 3;
        const float* src = mt ? (W_hh + 512 * HSZ) : (W_ih + 512 * HSZ);
        W1s[k * 32 + col] = __ldg(&src[(uStart + ul + g * HSZ) * HSZ + k]);
    }
    for (int i = tid; i < NOUT * HSZ; i += NTH) {
        int o = i >> 7, k = i & 127;
        WoT[k * 48 + o] = __ldg(&W_out[o * HSZ + k]);
    }
    if (tid < NOUT) bo[tid] = __ldg(&b_out[tid]);
    __syncthreads();

    const int bl = tid & 63;
    const int b  = b0 + bl;
    const int ul = tid >> 6;
    const int u  = uStart + ul;

    // out-projection assignment (precomputed: no per-step divide)
    const int od   = ug * 90 + tid;          // 32 u-groups * 90 = 64 b * 45 outs
    const int oblo = od / 45;
    const int oo   = od - oblo * 45;

    float c0r = 0.f, c1r = 0.f;   // cell states in registers for all 4096 steps

    const float4 mi = *reinterpret_cast<const float4*>(&g_Mf[(u        ) * 4]);
    const float4 mf = *reinterpret_cast<const float4*>(&g_Mf[(u + 128) * 4]);
    const float4 mg = *reinterpret_cast<const float4*>(&g_Mf[(u + 256) * 4]);
    const float4 mo = *reinterpret_cast<const float4*>(&g_Mf[(u + 384) * 4]);
    const unsigned long long bIF1 = pack2(g_bias1[u],       g_bias1[u + 128]);
    const unsigned long long bGO1 = pack2(g_bias1[u + 256], g_bias1[u + 384]);

    const float* xrow = x + b * 3 * TSEQ;

    for (int s = 0; s <= TSEQ + 1; ++s) {
        const int rp  = (s + 1) & 1;   // == (s-1)&1 : h0 prev parity
        const int rp2 = s & 1;         // == (s-2)&1 : h1 prev parity

        // prefetch pixel early so LDG latency hides under staging
        float px0 = 0.f, px1 = 0.f, px2 = 0.f;
        if (s < TSEQ) {
            px0 = __ldg(xrow + s);
            px1 = __ldg(xrow + TSEQ + s);
            px2 = __ldg(xrow + 2 * TSEQ + s);
        }

        // ---- stage h0_{s-1} and h1_{s-2} slices into SMEM
        for (int i = tid; i < HSZ * 16; i += NTH) {
            int k = i >> 4, c = i & 15;
            float4 v0 = __ldcg(reinterpret_cast<const float4*>(&g_h0T[(rp  * HSZ + k) * BATCH + b0]) + c);
            reinterpret_cast<float4*>(h0s)[i] = v0;
            float4 v1 = __ldcg(reinterpret_cast<const float4*>(&g_h1T[(rp2 * HSZ + k) * BATCH + b0]) + c);
            reinterpret_cast<float4*>(h1s)[i] = v1;
        }
        __syncthreads();

        // ---- layer 0, step s: gates = folded(px) + h0_{s-1} @ Whh0^T
        if (s < TSEQ) {
            unsigned long long aIF = 0ull, aGO = 0ull;   // packed (i,f), (g,o)
            const float* wp = W0s + ul * 4;
            const float* hp = h0s + bl;
            #pragma unroll 8
            for (int k = 0; k < HSZ; ++k) {
                unsigned long long hh = packdup(hp[k * 64]);
                ulonglong2 w2 = *reinterpret_cast<const ulonglong2*>(wp + k * 16);
                fma2(aIF, hh, w2.x);
                fma2(aGO, hh, w2.y);
            }
            float ai, af, ag, ao;
            unpack2(ai, af, aIF);
            unpack2(ag, ao, aGO);
            ai += mi.x * px0 + mi.y * px1 + mi.z * px2 + mi.w;
            af += mf.x * px0 + mf.y * px1 + mf.z * px2 + mf.w;
            ag += mg.x * px0 + mg.y * px1 + mg.z * px2 + mg.w;
            ao += mo.x * px0 + mo.y * px1 + mo.z * px2 + mo.w;
            float I = sigf(ai), F = sigf(af), G = tanh_(ag), O = sigf(ao);
            c0r = F * c0r + I * G;
            float h = O * tanh_(c0r);
            __stcg(&g_h0T[((s & 1) * HSZ + u) * BATCH + b], h);
        }

        // ---- layer 1, step s-1: gates = h0_{s-1} @ Wih1^T + h1_{s-2} @ Whh1^T
        if (s >= 1 && s <= TSEQ) {
            unsigned long long aIF0 = bIF1, aGO0 = bGO1;
            unsigned long long aIF1v = 0ull, aGO1v = 0ull;
            const float* wp1 = W1s + ul * 8;
            const float* hp0 = h0s + bl;
            const float* hp1 = h1s + bl;
            #pragma unroll 4
            for (int k = 0; k < HSZ; ++k) {
                unsigned long long h0p = packdup(hp0[k * 64]);
                unsigned long long h1p = packdup(hp1[k * 64]);
                ulonglong2 wi2 = *reinterpret_cast<const ulonglong2*>(wp1 + k * 32);
                ulonglong2 wh2 = *reinterpret_cast<const ulonglong2*>(wp1 + k * 32 + 4);
                fma2(aIF0, h0p, wi2.x);
                fma2(aGO0, h0p, wi2.y);
                fma2(aIF1v, h1p, wh2.x);
                fma2(aGO1v, h1p, wh2.y);
            }
            float ai0, af0, ag0, ao0, ai1, af1, ag1, ao1;
            unpack2(ai0, af0, aIF0);
            unpack2(ag0, ao0, aGO0);
            unpack2(ai1, af1, aIF1v);
            unpack2(ag1, ao1, aGO1v);
            float I = sigf(ai0 + ai1), F = sigf(af0 + af1);
            float G = tanh_(ag0 + ag1), O = sigf(ao0 + ao1);
            c1r = F * c1r + I * G;
            float h = O * tanh_(c1r);
            __stcg(&g_h1T[(((s - 1) & 1) * HSZ + u) * BATCH + b], h);
        }

        // ---- output projection, step s-2 (h1s staged buffer == h1_{s-2})
        if (s >= 2 && tid < 90) {
            float acc = bo[oo];
            const float* hp  = h1s + oblo;
            const float* wpo = WoT + oo;
            #pragma unroll 8
            for (int k = 0; k < HSZ; ++k) acc += hp[k * 64] * wpo[k * 48];
            out[(b0 + oblo) * (TSEQ * NOUT) + (s - 2) * NOUT + oo] = acc;
        }

        // ---- global barrier: flag release + parallel acquire-poll
        __syncthreads();
        const unsigned target = (unsigned)(s + 1);
        if (tid == 0) {
            asm volatile("st.global.release.gpu.u32 [%0], %1;"
                         :: "l"(&g_flags[blockIdx.x * 32]), "r"(target) : "memory");
        }
        if (tid < NCTA) {
            const unsigned int* fp = &g_flags[tid * 32];
            unsigned v;
            asm volatile("ld.global.acquire.gpu.u32 %0, [%1];" : "=r"(v) : "l"(fp) : "memory");
            while (v < target) {
                __nanosleep(64);
                asm volatile("ld.global.acquire.gpu.u32 %0, [%1];" : "=r"(v) : "l"(fp) : "memory");
            }
        }
        __syncthreads();
    }
}

extern "C" void kernel_launch(void* const* d_in, const int* in_sizes, int n_in,
                              void* d_out, int out_size) {
    const float* x     = (const float*)d_in[0];
    const float* W_in  = (const float*)d_in[1];
    const float* b_in  = (const float*)d_in[2];
    const float* W_ih  = (const float*)d_in[3];
    const float* W_hh  = (const float*)d_in[4];
    const float* b_ih  = (const float*)d_in[5];
    const float* b_hh  = (const float*)d_in[6];
    const float* W_out = (const float*)d_in[7];
    const float* b_out = (const float*)d_in[8];
    float* out = (float*)d_out;

    cudaFuncSetAttribute(lstm_persist, cudaFuncAttributeMaxDynamicSharedMemorySize, SMEM_BYTES);

    prep_kernel<<<64, 256>>>(W_in, b_in, W_ih, b_ih, b_hh);
    lstm_persist<<<NCTA, NTH, SMEM_BYTES>>>(x, W_ih, W_hh, W_out, b_out, out);
}

// round 8
// speedup vs baseline: 1.0997x; 1.0652x over previous
#include <cuda_runtime.h>

// PixelRNN: 2-layer LSTM, T=4096 steps, B=256, H=128, OUT=45.
// Persistent cooperative kernel. Per step: stage h to SMEM, k-split partial
// gate GEMMs across 512 threads (2x256), smem combine, epilogue, one global
// barrier per step (R3-proven: atomicAdd + threadfence + volatile spin).
// c-state in registers, weights in SMEM, h0/h1 double-buffered via L2 (.cg),
// packed fma.rn.f32x2 everywhere in the gate accumulations.
// Co-residency: 128 CTAs, 123KB dyn smem -> 1 CTA/SM, all wave-1 resident.

#define TSEQ   4096
#define BATCH  256
#define HSZ    128
#define NOUT   45
#define NCTA   128     // 4 batch tiles x 32 u-groups
#define NTH    512     // 256 (b,u) roles x 2 k-halves
#define BTILE  64      // batch rows per CTA
#define UPG    4       // hidden units per CTA

// ---- persistent device state ----
__device__ float g_h0T[2 * HSZ * BATCH];   // [parity][k][b]
__device__ float g_h1T[2 * HSZ * BATCH];
__device__ float g_Mf[512 * 4];            // folded input path: [j][c0,c1,c2,bias0]
__device__ float g_bias1[512];
__device__ unsigned int g_bar;

__global__ void prep_kernel(const float* __restrict__ W_in, const float* __restrict__ b_in,
                            const float* __restrict__ W_ih, const float* __restrict__ b_ih,
                            const float* __restrict__ b_hh) {
    int idx = blockIdx.x * blockDim.x + threadIdx.x;
    int stride = gridDim.x * blockDim.x;
    for (int i = idx; i < 2 * HSZ * BATCH; i += stride) {
        g_h0T[i] = 0.f;
        g_h1T[i] = 0.f;
    }
    if (idx == 0) g_bar = 0u;
    int j = idx;
    if (j < 512) {
        float m0 = 0.f, m1 = 0.f, m2 = 0.f, mb = 0.f;
        for (int k = 0; k < HSZ; ++k) {
            float w = W_ih[j * HSZ + k];             // layer 0
            m0 += w * W_in[k * 3 + 0];
            m1 += w * W_in[k * 3 + 1];
            m2 += w * W_in[k * 3 + 2];
            mb += w * b_in[k];
        }
        g_Mf[j * 4 + 0] = m0;
        g_Mf[j * 4 + 1] = m1;
        g_Mf[j * 4 + 2] = m2;
        g_Mf[j * 4 + 3] = mb + b_ih[j] + b_hh[j];
        g_bias1[j] = b_ih[512 + j] + b_hh[512 + j];
    }
}

__device__ __forceinline__ float sigf(float v)  { return 1.0f / (1.0f + __expf(-v)); }
__device__ __forceinline__ float tanh_(float v) { return 1.0f - 2.0f / (__expf(2.0f * v) + 1.0f); }

__device__ __forceinline__ unsigned long long pack2(float lo, float hi) {
    unsigned long long r;
    asm("mov.b64 %0, {%1, %2};" : "=l"(r) : "f"(lo), "f"(hi));
    return r;
}
__device__ __forceinline__ unsigned long long packdup(float v) {
    unsigned long long r;
    asm("mov.b64 %0, {%1, %1};" : "=l"(r) : "f"(v));
    return r;
}
__device__ __forceinline__ void fma2(unsigned long long& acc, unsigned long long a, unsigned long long b) {
    asm("fma.rn.f32x2 %0, %1, %2, %0;" : "+l"(acc) : "l"(a), "l"(b));
}
__device__ __forceinline__ void add2(unsigned long long& acc, unsigned long long a) {
    asm("add.rn.f32x2 %0, %0, %1;" : "+l"(acc) : "l"(a));
}
__device__ __forceinline__ void unpack2(float& lo, float& hi, unsigned long long v) {
    asm("mov.b64 {%0, %1}, %2;" : "=f"(lo), "=f"(hi) : "l"(v));
}

// SMEM layout (floats)
#define SM_H0S  0                    // [128][64]
#define SM_H1S  8192                 // [128][64]
#define SM_W0S  16384                // [128][16]  layer0 Whh slice, [k][ul*4+g] g=i,f,g,o
#define SM_W1S  18432                // [128][32]  layer1, [k][ul*8 + mat*4 + g]
#define SM_WOT  22528                // [128][48]  W_out^T padded
#define SM_BO   28672                // [48]
#define SM_PART 28720                // 256 x 4 ull = 2048 floats (k-split partials)
#define SM_FLOATS 30768
#define SMEM_BYTES (SM_FLOATS * 4)

__global__ void __launch_bounds__(NTH, 1) lstm_persist(
    const float* __restrict__ x,      // [B,3,64,64]
    const float* __restrict__ W_ih,   // [2,512,128]
    const float* __restrict__ W_hh,   // [2,512,128]
    const float* __restrict__ W_out,  // [45,128]
    const float* __restrict__ b_out,  // [45]
    float* __restrict__ out)          // [B,T,45]
{
    extern __shared__ float sm[];
    float* h0s = sm + SM_H0S;
    float* h1s = sm + SM_H1S;
    float* W0s = sm + SM_W0S;
    float* W1s = sm + SM_W1S;
    float* WoT = sm + SM_WOT;
    float* bo  = sm + SM_BO;
    unsigned long long* part = reinterpret_cast<unsigned long long*>(sm + SM_PART);

    const int tid = threadIdx.x;
    const int bt = blockIdx.x & 3;
    const int ug = blockIdx.x >> 2;        // 0..31
    const int b0 = bt * BTILE;
    const int uStart = ug * UPG;

    // ---- one-time weight staging ----
    for (int i = tid; i < 16 * HSZ; i += NTH) {
        int colg = i >> 7, k = i & 127;            // colg = ul*4+g
        int ul_ = colg >> 2, g = colg & 3;
        W0s[k * 16 + colg] = __ldg(&W_hh[(uStart + ul_ + g * HSZ) * HSZ + k]);  // layer0 hh
    }
    for (int i = tid; i < 32 * HSZ; i += NTH) {
        int col = i >> 7, k = i & 127;             // col = ul*8 + mat*4 + g
        int ul_ = col >> 3, mt = (col >> 2) & 1, g = col & 3;
        const float* src = mt ? (W_hh + 512 * HSZ) : (W_ih + 512 * HSZ);
        W1s[k * 32 + col] = __ldg(&src[(uStart + ul_ + g * HSZ) * HSZ + k]);
    }
    for (int i = tid; i < NOUT * HSZ; i += NTH) {
        int o = i >> 7, k = i & 127;
        WoT[k * 48 + o] = __ldg(&W_out[o * HSZ + k]);
    }
    if (tid < NOUT) bo[tid] = __ldg(&b_out[tid]);
    __syncthreads();

    const int p  = tid & 255;              // (b,u) role id
    const bool lower = (tid < 256);        // combiner half (owns state + epilogue)
    const int kbase = lower ? 0 : 64;      // k-split half
    const int bl = p & 63;
    const int b  = b0 + bl;
    const int ul = p >> 6;
    const int u  = uStart + ul;

    // out-projection assignment for upper half (utid in [0,90))
    const int utid = tid - 256;
    const int od   = ug * 90 + utid;       // 32 u-groups * 90 = 64 b * 45 outs
    const int oblo = (utid >= 0 && utid < 90) ? od / 45 : 0;
    const int oo   = (utid >= 0 && utid < 90) ? od - oblo * 45 : 0;

    float c0r = 0.f, c1r = 0.f;   // cell states (lower half) for all 4096 steps

    const float4 mi = *reinterpret_cast<const float4*>(&g_Mf[(u        ) * 4]);
    const float4 mf = *reinterpret_cast<const float4*>(&g_Mf[(u + 128) * 4]);
    const float4 mg = *reinterpret_cast<const float4*>(&g_Mf[(u + 256) * 4]);
    const float4 mo = *reinterpret_cast<const float4*>(&g_Mf[(u + 384) * 4]);
    const unsigned long long bIF1 = pack2(g_bias1[u],       g_bias1[u + 128]);
    const unsigned long long bGO1 = pack2(g_bias1[u + 256], g_bias1[u + 384]);

    const float* xrow = x + b * 3 * TSEQ;

    for (int s = 0; s <= TSEQ + 1; ++s) {
        const int rp  = (s + 1) & 1;   // == (s-1)&1 : h0 prev parity
        const int rp2 = s & 1;         // == (s-2)&1 : h1 prev parity

        // prefetch pixel early (lower half only needs it)
        float px0 = 0.f, px1 = 0.f, px2 = 0.f;
        if (lower && s < TSEQ) {
            px0 = __ldg(xrow + s);
            px1 = __ldg(xrow + TSEQ + s);
            px2 = __ldg(xrow + 2 * TSEQ + s);
        }

        // ---- stage h0_{s-1} and h1_{s-2} slices into SMEM (all 512 threads)
        for (int i = tid; i < HSZ * 16; i += NTH) {
            int k = i >> 4, c = i & 15;
            float4 v0 = __ldcg(reinterpret_cast<const float4*>(&g_h0T[(rp  * HSZ + k) * BATCH + b0]) + c);
            reinterpret_cast<float4*>(h0s)[i] = v0;
            float4 v1 = __ldcg(reinterpret_cast<const float4*>(&g_h1T[(rp2 * HSZ + k) * BATCH + b0]) + c);
            reinterpret_cast<float4*>(h1s)[i] = v1;
        }
        __syncthreads();

        // ---- partial gate sums over this thread's k-half
        unsigned long long l0IF = 0ull, l0GO = 0ull;
        unsigned long long a1IF = lower ? bIF1 : 0ull, a1GO = lower ? bGO1 : 0ull;
        unsigned long long b1IF = 0ull, b1GO = 0ull;

        if (s < TSEQ) {
            const float* wp = W0s + ul * 4 + kbase * 16;
            const float* hp = h0s + bl + kbase * 64;
            #pragma unroll 8
            for (int k = 0; k < 64; ++k) {
                unsigned long long hh = packdup(hp[k * 64]);
                ulonglong2 w2 = *reinterpret_cast<const ulonglong2*>(wp + k * 16);
                fma2(l0IF, hh, w2.x);
                fma2(l0GO, hh, w2.y);
            }
        }
        if (s >= 1 && s <= TSEQ) {
            const float* wp1 = W1s + ul * 8 + kbase * 32;
            const float* hp0 = h0s + bl + kbase * 64;
            const float* hp1 = h1s + bl + kbase * 64;
            #pragma unroll 8
            for (int k = 0; k < 64; ++k) {
                unsigned long long h0p = packdup(hp0[k * 64]);
                unsigned long long h1p = packdup(hp1[k * 64]);
                ulonglong2 wi2 = *reinterpret_cast<const ulonglong2*>(wp1 + k * 32);
                ulonglong2 wh2 = *reinterpret_cast<const ulonglong2*>(wp1 + k * 32 + 4);
                fma2(a1IF, h0p, wi2.x);
                fma2(a1GO, h0p, wi2.y);
                fma2(b1IF, h1p, wh2.x);
                fma2(b1GO, h1p, wh2.y);
            }
        }
        if (!lower) {
            add2(a1IF, b1IF);       // fold layer1 h0/h1 partials together
            add2(a1GO, b1GO);
            ulonglong2* pp = reinterpret_cast<ulonglong2*>(part + p * 4);
            pp[0] = make_ulonglong2(l0IF, l0GO);
            pp[1] = make_ulonglong2(a1IF, a1GO);
        }
        __syncthreads();

        if (lower) {
            const ulonglong2* pp = reinterpret_cast<const ulonglong2*>(part + p * 4);
            ulonglong2 q0 = pp[0], q1 = pp[1];

            // ---- layer 0 epilogue, step s
            if (s < TSEQ) {
                add2(l0IF, q0.x);
                add2(l0GO, q0.y);
                float ai, af, ag, ao;
                unpack2(ai, af, l0IF);
                unpack2(ag, ao, l0GO);
                ai += mi.x * px0 + mi.y * px1 + mi.z * px2 + mi.w;
                af += mf.x * px0 + mf.y * px1 + mf.z * px2 + mf.w;
                ag += mg.x * px0 + mg.y * px1 + mg.z * px2 + mg.w;
                ao += mo.x * px0 + mo.y * px1 + mo.z * px2 + mo.w;
                float I = sigf(ai), F = sigf(af), G = tanh_(ag), O = sigf(ao);
                c0r = F * c0r + I * G;
                float h = O * tanh_(c0r);
                __stcg(&g_h0T[((s & 1) * HSZ + u) * BATCH + b], h);
            }
            // ---- layer 1 epilogue, step s-1
            if (s >= 1 && s <= TSEQ) {
                add2(a1IF, b1IF);
                add2(a1GO, b1GO);
                add2(a1IF, q1.x);
                add2(a1GO, q1.y);
                float ai, af, ag, ao;
                unpack2(ai, af, a1IF);
                unpack2(ag, ao, a1GO);
                float I = sigf(ai), F = sigf(af), G = tanh_(ag), O = sigf(ao);
                c1r = F * c1r + I * G;
                float h = O * tanh_(c1r);
                __stcg(&g_h1T[(((s - 1) & 1) * HSZ + u) * BATCH + b], h);
            }
        } else {
            // ---- output projection, step s-2 (h1s staged buffer == h1_{s-2})
            if (s >= 2 && utid < 90) {
                float acc = bo[oo];
                const float* hp  = h1s + oblo;
                const float* wpo = WoT + oo;
                #pragma unroll 8
                for (int k = 0; k < HSZ; ++k) {
                    acc += (*hp) * (*wpo);
                    hp += 64; wpo += 48;
                }
                out[(b0 + oblo) * (TSEQ * NOUT) + (s - 2) * NOUT + oo] = acc;
            }
        }

        // ---- global barrier (R3-proven): atomicAdd arrive + volatile spin
        __syncthreads();
        if (tid == 0) {
            __threadfence();
            atomicAdd(&g_bar, 1u);
            const unsigned target = (unsigned)(s + 1) * (unsigned)NCTA;
            while (*reinterpret_cast<volatile unsigned*>(&g_bar) < target) {
                __nanosleep(64);
            }
            __threadfence();
        }
        __syncthreads();
    }
}

extern "C" void kernel_launch(void* const* d_in, const int* in_sizes, int n_in,
                              void* d_out, int out_size) {
    const float* x     = (const float*)d_in[0];
    const float* W_in  = (const float*)d_in[1];
    const float* b_in  = (const float*)d_in[2];
    const float* W_ih  = (const float*)d_in[3];
    const float* W_hh  = (const float*)d_in[4];
    const float* b_ih  = (const float*)d_in[5];
    const float* b_hh  = (const float*)d_in[6];
    const float* W_out = (const float*)d_in[7];
    const float* b_out = (const float*)d_in[8];
    float* out = (float*)d_out;

    cudaFuncSetAttribute(lstm_persist, cudaFuncAttributeMaxDynamicSharedMemorySize, SMEM_BYTES);

    prep_kernel<<<64, 256>>>(W_in, b_in, W_ih, b_ih, b_hh);
    lstm_persist<<<NCTA, NTH, SMEM_BYTES>>>(x, W_ih, W_hh, W_out, b_out, out);
}

// round 9
// speedup vs baseline: 1.1802x; 1.0732x over previous
#include <cuda_runtime.h>

// PixelRNN: 2-layer LSTM, T=4096 steps, B=256, H=128, OUT=45.
// Persistent cooperative kernel. Register-blocked GEMM: 256 threads =
// 64 batch-lanes x 4 k-quarters; each thread computes ALL 4 units' gates for
// its k-range (one h load feeds 8-16 FFMA2 -> 4x less smem h traffic).
// Partials combined via transposed smem layout; combine phase = per-(bl,ul)
// epilogue with c-state in registers. One proven global barrier per step.
// Co-residency: 128 CTAs, ~145KB dyn smem -> 1 CTA/SM, all wave-1 resident.

#define TSEQ   4096
#define BATCH  256
#define HSZ    128
#define NOUT   45
#define NCTA   128     // 4 batch tiles x 32 u-groups
#define NTH    256
#define BTILE  64      // batch rows per CTA
#define UPG    4       // hidden units per CTA

typedef unsigned long long ull;

// ---- persistent device state ----
__device__ float g_h0T[2 * HSZ * BATCH];   // [parity][k][b]
__device__ float g_h1T[2 * HSZ * BATCH];
__device__ float g_Mf[512 * 4];            // folded input path: [j][c0,c1,c2,bias0]
__device__ float g_bias1[512];
__device__ unsigned int g_bar;

__global__ void prep_kernel(const float* __restrict__ W_in, const float* __restrict__ b_in,
                            const float* __restrict__ W_ih, const float* __restrict__ b_ih,
                            const float* __restrict__ b_hh) {
    int idx = blockIdx.x * blockDim.x + threadIdx.x;
    int stride = gridDim.x * blockDim.x;
    for (int i = idx; i < 2 * HSZ * BATCH; i += stride) {
        g_h0T[i] = 0.f;
        g_h1T[i] = 0.f;
    }
    if (idx == 0) g_bar = 0u;
    int j = idx;
    if (j < 512) {
        float m0 = 0.f, m1 = 0.f, m2 = 0.f, mb = 0.f;
        for (int k = 0; k < HSZ; ++k) {
            float w = W_ih[j * HSZ + k];             // layer 0
            m0 += w * W_in[k * 3 + 0];
            m1 += w * W_in[k * 3 + 1];
            m2 += w * W_in[k * 3 + 2];
            mb += w * b_in[k];
        }
        g_Mf[j * 4 + 0] = m0;
        g_Mf[j * 4 + 1] = m1;
        g_Mf[j * 4 + 2] = m2;
        g_Mf[j * 4 + 3] = mb + b_ih[j] + b_hh[j];
        g_bias1[j] = b_ih[512 + j] + b_hh[512 + j];
    }
}

__device__ __forceinline__ float sigf(float v)  { return 1.0f / (1.0f + __expf(-v)); }
__device__ __forceinline__ float tanh_(float v) { return 1.0f - 2.0f / (__expf(2.0f * v) + 1.0f); }

__device__ __forceinline__ ull pack2(float lo, float hi) {
    ull r;
    asm("mov.b64 %0, {%1, %2};" : "=l"(r) : "f"(lo), "f"(hi));
    return r;
}
__device__ __forceinline__ ull packdup(float v) {
    ull r;
    asm("mov.b64 %0, {%1, %1};" : "=l"(r) : "f"(v));
    return r;
}
__device__ __forceinline__ void fma2(ull& acc, ull a, ull b) {
    asm("fma.rn.f32x2 %0, %1, %2, %0;" : "+l"(acc) : "l"(a), "l"(b));
}
__device__ __forceinline__ void add2(ull& acc, ull a) {
    asm("add.rn.f32x2 %0, %0, %1;" : "+l"(acc) : "l"(a));
}
__device__ __forceinline__ void unpack2(float& lo, float& hi, ull v) {
    asm("mov.b64 {%0, %1}, %2;" : "=f"(lo), "=f"(hi) : "l"(v));
}

// SMEM layout (floats)
#define SM_H0S   0                   // [128][64]   h0_{s-1}
#define SM_H1S   8192                // [128][64]   h1_{s-2}
#define SM_W0S   16384               // [128][16]   layer0 Whh slice [k][ul*4+g]
#define SM_W1S   18432               // [128][32]   layer1 [k][ul*8 + mat*4 + g]
#define SM_WOT   22528               // [128][48]   W_out^T padded
#define SM_BO    28672               // [48]
#define SM_OPART 28720               // [192]       out-proj half-dot partials
#define SM_PART  28912               // 16*256 ull  gate partials [j][cell]
#define SM_FLOATS (28912 + 16 * 256 * 2)
#define SMEM_BYTES (SM_FLOATS * 4)

__global__ void __launch_bounds__(NTH, 1) lstm_persist(
    const float* __restrict__ x,      // [B,3,64,64]
    const float* __restrict__ W_ih,   // [2,512,128]
    const float* __restrict__ W_hh,   // [2,512,128]
    const float* __restrict__ W_out,  // [45,128]
    const float* __restrict__ b_out,  // [45]
    float* __restrict__ out)          // [B,T,45]
{
    extern __shared__ float sm[];
    float* h0s = sm + SM_H0S;
    float* h1s = sm + SM_H1S;
    float* W0s = sm + SM_W0S;
    float* W1s = sm + SM_W1S;
    float* WoT = sm + SM_WOT;
    float* bo  = sm + SM_BO;
    float* opart = sm + SM_OPART;
    ull* part = reinterpret_cast<ull*>(sm + SM_PART);

    const int tid = threadIdx.x;
    const int bt = blockIdx.x & 3;
    const int ug = blockIdx.x >> 2;        // 0..31
    const int b0 = bt * BTILE;
    const int uStart = ug * UPG;

    // ---- one-time weight staging ----
    for (int i = tid; i < 16 * HSZ; i += NTH) {
        int colg = i >> 7, k = i & 127;            // colg = ul*4+g
        int ul_ = colg >> 2, g = colg & 3;
        W0s[k * 16 + colg] = __ldg(&W_hh[(uStart + ul_ + g * HSZ) * HSZ + k]);  // layer0 hh
    }
    for (int i = tid; i < 32 * HSZ; i += NTH) {
        int col = i >> 7, k = i & 127;             // col = ul*8 + mat*4 + g
        int ul_ = col >> 3, mt = (col >> 2) & 1, g = col & 3;
        const float* src = mt ? (W_hh + 512 * HSZ) : (W_ih + 512 * HSZ);
        W1s[k * 32 + col] = __ldg(&src[(uStart + ul_ + g * HSZ) * HSZ + k]);
    }
    for (int i = tid; i < NOUT * HSZ; i += NTH) {
        int o = i >> 7, k = i & 127;
        WoT[k * 48 + o] = __ldg(&W_out[o * HSZ + k]);
    }
    if (tid < NOUT) bo[tid] = __ldg(&b_out[tid]);
    __syncthreads();

    const int bl = tid & 63;               // batch lane (GEMM + combine role)
    const int kq = tid >> 6;               // k-quarter (GEMM role)
    const int kb = kq * 32;
    const int ul = tid >> 6;               // unit (combine role)
    const int b  = b0 + bl;
    const int u  = uStart + ul;

    // out-projection half-dot role (tid < 180): pair p2, k-half kh
    const int p2 = tid >> 1;
    const int kh = (tid & 1) * 64;
    const int d1   = ug * 90 + p2;
    const int ob1  = d1 / 45;
    const int oo1  = d1 - ob1 * 45;
    // out-projection final role (tid < 90)
    const int d2   = ug * 90 + tid;
    const int ob2  = d2 / 45;
    const int oo2  = d2 - ob2 * 45;

    float c0r = 0.f, c1r = 0.f;   // cell states (per (bl,ul) cell) for all steps

    const float4 mi = *reinterpret_cast<const float4*>(&g_Mf[(u        ) * 4]);
    const float4 mf = *reinterpret_cast<const float4*>(&g_Mf[(u + 128) * 4]);
    const float4 mg = *reinterpret_cast<const float4*>(&g_Mf[(u + 256) * 4]);
    const float4 mo = *reinterpret_cast<const float4*>(&g_Mf[(u + 384) * 4]);
    const ull bIF1 = pack2(g_bias1[u],       g_bias1[u + 128]);
    const ull bGO1 = pack2(g_bias1[u + 256], g_bias1[u + 384]);

    const float* xrow = x + b * 3 * TSEQ;

    for (int s = 0; s <= TSEQ + 1; ++s) {
        const int rp  = (s + 1) & 1;   // == (s-1)&1 : h0 prev parity
        const int rp2 = s & 1;         // == (s-2)&1 : h1 prev parity

        // prefetch pixel early (every thread is combiner for its bl)
        float px0 = 0.f, px1 = 0.f, px2 = 0.f;
        if (s < TSEQ) {
            px0 = __ldg(xrow + s);
            px1 = __ldg(xrow + TSEQ + s);
            px2 = __ldg(xrow + 2 * TSEQ + s);
        }

        // ---- stage h0_{s-1} and h1_{s-2} slices into SMEM
        for (int i = tid; i < HSZ * 16; i += NTH) {
            int k = i >> 4, c = i & 15;
            float4 v0 = __ldcg(reinterpret_cast<const float4*>(&g_h0T[(rp  * HSZ + k) * BATCH + b0]) + c);
            reinterpret_cast<float4*>(h0s)[i] = v0;
            float4 v1 = __ldcg(reinterpret_cast<const float4*>(&g_h1T[(rp2 * HSZ + k) * BATCH + b0]) + c);
            reinterpret_cast<float4*>(h1s)[i] = v1;
        }
        __syncthreads();

        // ---- register-blocked partial GEMMs over this thread's k-quarter
        ull a0IF[UPG] = {0,0,0,0}, a0GO[UPG] = {0,0,0,0};
        ull a1IF[UPG] = {0,0,0,0}, a1GO[UPG] = {0,0,0,0};

        if (s < TSEQ) {
            const float* hp = h0s + bl;
            #pragma unroll 4
            for (int k = 0; k < 32; ++k) {
                int kk = kb + k;
                ull hh = packdup(hp[kk * 64]);
                const ulonglong2* wr = reinterpret_cast<const ulonglong2*>(W0s + kk * 16);
                #pragma unroll
                for (int uu = 0; uu < UPG; ++uu) {
                    ulonglong2 w2 = wr[uu];
                    fma2(a0IF[uu], hh, w2.x);
                    fma2(a0GO[uu], hh, w2.y);
                }
            }
        }
        if (s >= 1 && s <= TSEQ) {
            const float* hp0 = h0s + bl;
            const float* hp1 = h1s + bl;
            #pragma unroll 4
            for (int k = 0; k < 32; ++k) {
                int kk = kb + k;
                ull h0p = packdup(hp0[kk * 64]);
                ull h1p = packdup(hp1[kk * 64]);
                const ulonglong2* wr = reinterpret_cast<const ulonglong2*>(W1s + kk * 32);
                #pragma unroll
                for (int uu = 0; uu < UPG; ++uu) {
                    ulonglong2 wi2 = wr[2 * uu];
                    ulonglong2 wh2 = wr[2 * uu + 1];
                    fma2(a1IF[uu], h0p, wi2.x);
                    fma2(a1GO[uu], h0p, wi2.y);
                    fma2(a1IF[uu], h1p, wh2.x);
                    fma2(a1GO[uu], h1p, wh2.y);
                }
            }
        }

        // ---- out-projection half-dot (step s-2), 180 threads
        float oacc = 0.f;
        if (s >= 2 && tid < 180) {
            const float* hp  = h1s + kh * 64 + ob1;
            const float* wpo = WoT + kh * 48 + oo1;
            #pragma unroll 8
            for (int k = 0; k < 64; ++k) {
                oacc += (*hp) * (*wpo);
                hp += 64; wpo += 48;
            }
        }

        // ---- store partials: part[j][cell], cell == tid (kq*64+bl)
        {
            ull* pb = part + tid;
            #pragma unroll
            for (int uu = 0; uu < UPG; ++uu) {
                pb[(uu * 4 + 0) * 256] = a0IF[uu];
                pb[(uu * 4 + 1) * 256] = a0GO[uu];
                pb[(uu * 4 + 2) * 256] = a1IF[uu];
                pb[(uu * 4 + 3) * 256] = a1GO[uu];
            }
            if (s >= 2 && tid < 180) opart[tid] = oacc;
        }
        __syncthreads();

        // ---- combine + epilogue: this thread owns cell (bl, ul)
        {
            ull s0 = 0, s1 = 0, s2 = 0, s3 = 0;
            const int jb = (ul * 4) * 256 + bl;
            #pragma unroll
            for (int q = 0; q < 4; ++q) {
                int c0 = jb + q * 64;
                add2(s0, part[c0]);
                add2(s1, part[c0 + 256]);
                add2(s2, part[c0 + 512]);
                add2(s3, part[c0 + 768]);
            }

            // layer 0 epilogue, step s
            if (s < TSEQ) {
                float ai, af, ag, ao;
                unpack2(ai, af, s0);
                unpack2(ag, ao, s1);
                ai += mi.x * px0 + mi.y * px1 + mi.z * px2 + mi.w;
                af += mf.x * px0 + mf.y * px1 + mf.z * px2 + mf.w;
                ag += mg.x * px0 + mg.y * px1 + mg.z * px2 + mg.w;
                ao += mo.x * px0 + mo.y * px1 + mo.z * px2 + mo.w;
                float I = sigf(ai), F = sigf(af), G = tanh_(ag), O = sigf(ao);
                c0r = F * c0r + I * G;
                float h = O * tanh_(c0r);
                __stcg(&g_h0T[((s & 1) * HSZ + u) * BATCH + b], h);
            }
            // layer 1 epilogue, step s-1
            if (s >= 1 && s <= TSEQ) {
                add2(s2, bIF1);
                add2(s3, bGO1);
                float ai, af, ag, ao;
                unpack2(ai, af, s2);
                unpack2(ag, ao, s3);
                float I = sigf(ai), F = sigf(af), G = tanh_(ag), O = sigf(ao);
                c1r = F * c1r + I * G;
                float h = O * tanh_(c1r);
                __stcg(&g_h1T[(((s - 1) & 1) * HSZ + u) * BATCH + b], h);
            }
            // out-projection final add, step s-2
            if (s >= 2 && tid < 90) {
                float acc = opart[2 * tid] + opart[2 * tid + 1] + bo[oo2];
                out[(b0 + ob2) * (TSEQ * NOUT) + (s - 2) * NOUT + oo2] = acc;
            }
        }

        // ---- global barrier (proven): atomicAdd + fence + volatile spin
        __syncthreads();
        if (tid == 0) {
            __threadfence();
            atomicAdd(&g_bar, 1u);
            const unsigned target = (unsigned)(s + 1) * (unsigned)NCTA;
            while (*reinterpret_cast<volatile unsigned*>(&g_bar) < target) {
                __nanosleep(64);
            }
            __threadfence();
        }
        __syncthreads();
    }
}

extern "C" void kernel_launch(void* const* d_in, const int* in_sizes, int n_in,
                              void* d_out, int out_size) {
    const float* x     = (const float*)d_in[0];
    const float* W_in  = (const float*)d_in[1];
    const float* b_in  = (const float*)d_in[2];
    const float* W_ih  = (const float*)d_in[3];
    const float* W_hh  = (const float*)d_in[4];
    const float* b_ih  = (const float*)d_in[5];
    const float* b_hh  = (const float*)d_in[6];
    const float* W_out = (const float*)d_in[7];
    const float* b_out = (const float*)d_in[8];
    float* out = (float*)d_out;

    cudaFuncSetAttribute(lstm_persist, cudaFuncAttributeMaxDynamicSharedMemorySize, SMEM_BYTES);

    prep_kernel<<<64, 256>>>(W_in, b_in, W_ih, b_ih, b_hh);
    lstm_persist<<<NCTA, NTH, SMEM_BYTES>>>(x, W_ih, W_hh, W_out, b_out, out);
}

// round 10
// speedup vs baseline: 1.3374x; 1.1332x over previous
#include <cuda_runtime.h>

// PixelRNN: 2-layer LSTM, T=4096 steps, B=256, H=128, OUT=45.
// Persistent cooperative kernel. GEMM: 8 warps = 8 k-eighths; each lane
// covers TWO batch rows (l, l+32) so every weight broadcast feeds 4 FFMA2
// (halves w-wavefront traffic, the measured bottleneck). Partials exchanged
// via conflict-free [slot][bl] smem layout. Merged l0+l1 loop. Epilogue per
// (bl,u) cell with c-state in registers. Proven global barrier per step.
// Co-residency: 128 CTAs, ~181KB dyn smem -> 1 CTA/SM, wave-1 resident.

#define TSEQ   4096
#define BATCH  256
#define HSZ    128
#define NOUT   45
#define NCTA   128     // 4 batch tiles x 32 u-groups
#define NTH    256
#define BTILE  64      // batch rows per CTA
#define UPG    4       // hidden units per CTA

typedef unsigned long long ull;

// ---- persistent device state ----
__device__ float g_h0T[2 * HSZ * BATCH];   // [parity][k][b]
__device__ float g_h1T[2 * HSZ * BATCH];
__device__ float g_Mf[512 * 4];            // folded input path: [j][c0,c1,c2,bias0]
__device__ float g_bias1[512];
__device__ unsigned int g_bar;

__global__ void prep_kernel(const float* __restrict__ W_in, const float* __restrict__ b_in,
                            const float* __restrict__ W_ih, const float* __restrict__ b_ih,
                            const float* __restrict__ b_hh) {
    int idx = blockIdx.x * blockDim.x + threadIdx.x;
    int stride = gridDim.x * blockDim.x;
    for (int i = idx; i < 2 * HSZ * BATCH; i += stride) {
        g_h0T[i] = 0.f;
        g_h1T[i] = 0.f;
    }
    if (idx == 0) g_bar = 0u;
    int j = idx;
    if (j < 512) {
        float m0 = 0.f, m1 = 0.f, m2 = 0.f, mb = 0.f;
        for (int k = 0; k < HSZ; ++k) {
            float w = W_ih[j * HSZ + k];             // layer 0
            m0 += w * W_in[k * 3 + 0];
            m1 += w * W_in[k * 3 + 1];
            m2 += w * W_in[k * 3 + 2];
            mb += w * b_in[k];
        }
        g_Mf[j * 4 + 0] = m0;
        g_Mf[j * 4 + 1] = m1;
        g_Mf[j * 4 + 2] = m2;
        g_Mf[j * 4 + 3] = mb + b_ih[j] + b_hh[j];
        g_bias1[j] = b_ih[512 + j] + b_hh[512 + j];
    }
}

__device__ __forceinline__ float sigf(float v)  { return 1.0f / (1.0f + __expf(-v)); }
__device__ __forceinline__ float tanh_(float v) { return 1.0f - 2.0f / (__expf(2.0f * v) + 1.0f); }

__device__ __forceinline__ ull pack2(float lo, float hi) {
    ull r;
    asm("mov.b64 %0, {%1, %2};" : "=l"(r) : "f"(lo), "f"(hi));
    return r;
}
__device__ __forceinline__ ull packdup(float v) {
    ull r;
    asm("mov.b64 %0, {%1, %1};" : "=l"(r) : "f"(v));
    return r;
}
__device__ __forceinline__ void fma2(ull& acc, ull a, ull b) {
    asm("fma.rn.f32x2 %0, %1, %2, %0;" : "+l"(acc) : "l"(a), "l"(b));
}
__device__ __forceinline__ void add2(ull& acc, ull a) {
    asm("add.rn.f32x2 %0, %0, %1;" : "+l"(acc) : "l"(a));
}
__device__ __forceinline__ void unpack2(float& lo, float& hi, ull v) {
    asm("mov.b64 {%0, %1}, %2;" : "=f"(lo), "=f"(hi) : "l"(v));
}

// SMEM layout (floats)
#define SM_H0S   0                   // [128][64]   h0_{s-1}
#define SM_H1S   8192                // [128][64]   h1_{s-2}
#define SM_W0S   16384               // [128][16]   layer0 Whh slice [k][ul*4+g]
#define SM_W1S   18432               // [128][32]   layer1 [k][ul*8 + mat*4 + g]
#define SM_WOT   22528               // [128][48]   W_out^T padded
#define SM_BO    28672               // [48]
#define SM_OPART 28720               // [192]       out-proj half-dot partials
#define SM_PART  28912               // 8192 ull: partials [ (u*4+g2)*8 + w ][ bl ]
#define SM_FLOATS (28912 + 8192 * 2)
#define SMEM_BYTES (SM_FLOATS * 4)

__global__ void __launch_bounds__(NTH, 1) lstm_persist(
    const float* __restrict__ x,      // [B,3,64,64]
    const float* __restrict__ W_ih,   // [2,512,128]
    const float* __restrict__ W_hh,   // [2,512,128]
    const float* __restrict__ W_out,  // [45,128]
    const float* __restrict__ b_out,  // [45]
    float* __restrict__ out)          // [B,T,45]
{
    extern __shared__ float sm[];
    float* h0s = sm + SM_H0S;
    float* h1s = sm + SM_H1S;
    float* W0s = sm + SM_W0S;
    float* W1s = sm + SM_W1S;
    float* WoT = sm + SM_WOT;
    float* bo  = sm + SM_BO;
    float* opart = sm + SM_OPART;
    ull* part = reinterpret_cast<ull*>(sm + SM_PART);

    const int tid = threadIdx.x;
    const int bt = blockIdx.x & 3;
    const int ug = blockIdx.x >> 2;        // 0..31
    const int b0 = bt * BTILE;
    const int uStart = ug * UPG;

    // ---- one-time weight staging ----
    for (int i = tid; i < 16 * HSZ; i += NTH) {
        int colg = i >> 7, k = i & 127;            // colg = ul*4+g
        int ul_ = colg >> 2, g = colg & 3;
        W0s[k * 16 + colg] = __ldg(&W_hh[(uStart + ul_ + g * HSZ) * HSZ + k]);  // layer0 hh
    }
    for (int i = tid; i < 32 * HSZ; i += NTH) {
        int col = i >> 7, k = i & 127;             // col = ul*8 + mat*4 + g
        int ul_ = col >> 3, mt = (col >> 2) & 1, g = col & 3;
        const float* src = mt ? (W_hh + 512 * HSZ) : (W_ih + 512 * HSZ);
        W1s[k * 32 + col] = __ldg(&src[(uStart + ul_ + g * HSZ) * HSZ + k]);
    }
    for (int i = tid; i < NOUT * HSZ; i += NTH) {
        int o = i >> 7, k = i & 127;
        WoT[k * 48 + o] = __ldg(&W_out[o * HSZ + k]);
    }
    if (tid < NOUT) bo[tid] = __ldg(&b_out[tid]);
    __syncthreads();

    // GEMM role: warp = k-eighth, lane covers bl = lane and lane+32
    const int wid  = tid >> 5;
    const int lane = tid & 31;
    const int kb   = wid * 16;

    // combine role: cell (bl, ul)
    const int bl = tid & 63;
    const int ul = tid >> 6;
    const int b  = b0 + bl;
    const int u  = uStart + ul;

    // out-projection half-dot role (tid < 180): pair p2, k-half kh
    const int p2 = tid >> 1;
    const int kh = (tid & 1) * 64;
    const int d1   = ug * 90 + p2;
    const int ob1  = d1 / 45;
    const int oo1  = d1 - ob1 * 45;
    // out-projection final role (tid < 90)
    const int d2   = ug * 90 + tid;
    const int ob2  = d2 / 45;
    const int oo2  = d2 - ob2 * 45;

    float c0r = 0.f, c1r = 0.f;   // cell states (per (bl,ul) cell) for all steps

    const float4 mi = *reinterpret_cast<const float4*>(&g_Mf[(u        ) * 4]);
    const float4 mf = *reinterpret_cast<const float4*>(&g_Mf[(u + 128) * 4]);
    const float4 mg = *reinterpret_cast<const float4*>(&g_Mf[(u + 256) * 4]);
    const float4 mo = *reinterpret_cast<const float4*>(&g_Mf[(u + 384) * 4]);
    const ull bIF1 = pack2(g_bias1[u],       g_bias1[u + 128]);
    const ull bGO1 = pack2(g_bias1[u + 256], g_bias1[u + 384]);

    const float* xrow = x + b * 3 * TSEQ;

    for (int s = 0; s <= TSEQ + 1; ++s) {
        const int rp  = (s + 1) & 1;   // == (s-1)&1 : h0 prev parity
        const int rp2 = s & 1;         // == (s-2)&1 : h1 prev parity

        // prefetch pixel early (combine role needs it)
        float px0 = 0.f, px1 = 0.f, px2 = 0.f;
        if (s < TSEQ) {
            px0 = __ldg(xrow + s);
            px1 = __ldg(xrow + TSEQ + s);
            px2 = __ldg(xrow + 2 * TSEQ + s);
        }

        // ---- stage h0_{s-1} and h1_{s-2} slices into SMEM
        for (int i = tid; i < HSZ * 16; i += NTH) {
            int k = i >> 4, c = i & 15;
            float4 v0 = __ldcg(reinterpret_cast<const float4*>(&g_h0T[(rp  * HSZ + k) * BATCH + b0]) + c);
            reinterpret_cast<float4*>(h0s)[i] = v0;
            float4 v1 = __ldcg(reinterpret_cast<const float4*>(&g_h1T[(rp2 * HSZ + k) * BATCH + b0]) + c);
            reinterpret_cast<float4*>(h1s)[i] = v1;
        }
        __syncthreads();

        // ---- merged l0+l1 partial GEMM over this warp's k-eighth,
        //      two batch rows per lane (runs unconditionally; edges are
        //      harmless because h buffers are zero / results are gated)
        ull A0IF[UPG] = {0,0,0,0}, A0GO[UPG] = {0,0,0,0};
        ull A1IF[UPG] = {0,0,0,0}, A1GO[UPG] = {0,0,0,0};
        ull B0IF[UPG] = {0,0,0,0}, B0GO[UPG] = {0,0,0,0};
        ull B1IF[UPG] = {0,0,0,0}, B1GO[UPG] = {0,0,0,0};

        {
            const float* h0p = h0s + kb * 64;
            const float* h1p = h1s + kb * 64;
            #pragma unroll 4
            for (int k = 0; k < 16; ++k) {
                const float* hr0 = h0p + k * 64;
                const float* hr1 = h1p + k * 64;
                ull h0a = packdup(hr0[lane]);
                ull h0b = packdup(hr0[lane + 32]);
                ull h1a = packdup(hr1[lane]);
                ull h1b = packdup(hr1[lane + 32]);
                const ulonglong2* w0r = reinterpret_cast<const ulonglong2*>(W0s + (kb + k) * 16);
                const ulonglong2* w1r = reinterpret_cast<const ulonglong2*>(W1s + (kb + k) * 32);
                #pragma unroll
                for (int uu = 0; uu < UPG; ++uu) {
                    ulonglong2 w0 = w0r[uu];
                    fma2(A0IF[uu], h0a, w0.x); fma2(A0GO[uu], h0a, w0.y);
                    fma2(B0IF[uu], h0b, w0.x); fma2(B0GO[uu], h0b, w0.y);
                    ulonglong2 wi = w1r[2 * uu];
                    ulonglong2 wh = w1r[2 * uu + 1];
                    fma2(A1IF[uu], h0a, wi.x); fma2(A1GO[uu], h0a, wi.y);
                    fma2(A1IF[uu], h1a, wh.x); fma2(A1GO[uu], h1a, wh.y);
                    fma2(B1IF[uu], h0b, wi.x); fma2(B1GO[uu], h0b, wi.y);
                    fma2(B1IF[uu], h1b, wh.x); fma2(B1GO[uu], h1b, wh.y);
                }
            }
        }

        // ---- out-projection half-dot (step s-2), 180 threads
        float oacc = 0.f;
        if (s >= 2 && tid < 180) {
            const float* hp  = h1s + kh * 64 + ob1;
            const float* wpo = WoT + kh * 48 + oo1;
            #pragma unroll 8
            for (int k = 0; k < 64; ++k) {
                oacc += (*hp) * (*wpo);
                hp += 64; wpo += 48;
            }
        }

        // ---- store partials: part[(u*4+g2)*8 + w][bl]  (stride-1 lanes)
        {
            #pragma unroll
            for (int uu = 0; uu < UPG; ++uu) {
                ull* r0 = part + ((uu * 4 + 0) * 8 + wid) * 64;
                ull* r1 = part + ((uu * 4 + 1) * 8 + wid) * 64;
                ull* r2 = part + ((uu * 4 + 2) * 8 + wid) * 64;
                ull* r3 = part + ((uu * 4 + 3) * 8 + wid) * 64;
                r0[lane] = A0IF[uu];  r0[lane + 32] = B0IF[uu];
                r1[lane] = A0GO[uu];  r1[lane + 32] = B0GO[uu];
                r2[lane] = A1IF[uu];  r2[lane + 32] = B1IF[uu];
                r3[lane] = A1GO[uu];  r3[lane + 32] = B1GO[uu];
            }
            if (s >= 2 && tid < 180) opart[tid] = oacc;
        }
        __syncthreads();

        // ---- combine + epilogue: this thread owns cell (bl, ul)
        {
            ull s0 = 0, s1 = 0, s2 = 0, s3 = 0;
            #pragma unroll
            for (int w = 0; w < 8; ++w) {
                add2(s0, part[((ul * 4 + 0) * 8 + w) * 64 + bl]);
                add2(s1, part[((ul * 4 + 1) * 8 + w) * 64 + bl]);
                add2(s2, part[((ul * 4 + 2) * 8 + w) * 64 + bl]);
                add2(s3, part[((ul * 4 + 3) * 8 + w) * 64 + bl]);
            }

            // layer 0 epilogue, step s
            if (s < TSEQ) {
                float ai, af, ag, ao;
                unpack2(ai, af, s0);
                unpack2(ag, ao, s1);
                ai += mi.x * px0 + mi.y * px1 + mi.z * px2 + mi.w;
                af += mf.x * px0 + mf.y * px1 + mf.z * px2 + mf.w;
                ag += mg.x * px0 + mg.y * px1 + mg.z * px2 + mg.w;
                ao += mo.x * px0 + mo.y * px1 + mo.z * px2 + mo.w;
                float I = sigf(ai), F = sigf(af), G = tanh_(ag), O = sigf(ao);
                c0r = F * c0r + I * G;
                float h = O * tanh_(c0r);
                __stcg(&g_h0T[((s & 1) * HSZ + u) * BATCH + b], h);
            }
            // layer 1 epilogue, step s-1
            if (s >= 1 && s <= TSEQ) {
                add2(s2, bIF1);
                add2(s3, bGO1);
                float ai, af, ag, ao;
                unpack2(ai, af, s2);
                unpack2(ag, ao, s3);
                float I = sigf(ai), F = sigf(af), G = tanh_(ag), O = sigf(ao);
                c1r = F * c1r + I * G;
                float h = O * tanh_(c1r);
                __stcg(&g_h1T[(((s - 1) & 1) * HSZ + u) * BATCH + b], h);
            }
            // out-projection final add, step s-2
            if (s >= 2 && tid < 90) {
                float acc = opart[2 * tid] + opart[2 * tid + 1] + bo[oo2];
                out[(b0 + ob2) * (TSEQ * NOUT) + (s - 2) * NOUT + oo2] = acc;
            }
        }

        // ---- global barrier (proven): atomicAdd + fence + volatile spin
        __syncthreads();
        if (tid == 0) {
            __threadfence();
            atomicAdd(&g_bar, 1u);
            const unsigned target = (unsigned)(s + 1) * (unsigned)NCTA;
            while (*reinterpret_cast<volatile unsigned*>(&g_bar) < target) {
                __nanosleep(64);
            }
            __threadfence();
        }
        __syncthreads();
    }
}

extern "C" void kernel_launch(void* const* d_in, const int* in_sizes, int n_in,
                              void* d_out, int out_size) {
    const float* x     = (const float*)d_in[0];
    const float* W_in  = (const float*)d_in[1];
    const float* b_in  = (const float*)d_in[2];
    const float* W_ih  = (const float*)d_in[3];
    const float* W_hh  = (const float*)d_in[4];
    const float* b_ih  = (const float*)d_in[5];
    const float* b_hh  = (const float*)d_in[6];
    const float* W_out = (const float*)d_in[7];
    const float* b_out = (const float*)d_in[8];
    float* out = (float*)d_out;

    cudaFuncSetAttribute(lstm_persist, cudaFuncAttributeMaxDynamicSharedMemorySize, SMEM_BYTES);

    prep_kernel<<<64, 256>>>(W_in, b_in, W_ih, b_ih, b_hh);
    lstm_persist<<<NCTA, NTH, SMEM_BYTES>>>(x, W_ih, W_hh, W_out, b_out, out);
}